// round 13
// baseline (speedup 1.0000x reference)
#include <cuda_runtime.h>
#include <cuda_fp16.h>
#include <math.h>
#include <cstdint>

#define BB 8
#define NN 4096
#define CC 768
#define HN 12
#define HD 64
#define ROWS (BB*NN)
#define EPSV 1e-6f

// ---- HMMA GEMM tiling ----
#define TM 128
#define TN 128
#define KC 64
#define NCHUNK (CC/KC)             // 12
#define ROWB 144                   // padded smem row stride (bytes) for 64 fp16
#define TILE_BYTES (128*ROWB)      // 18432
#define STAGE_BYTES (4*TILE_BYTES) // Ah,Al,Bh,Bl = 73728
#define SM_TOTAL (2*STAGE_BYTES)   // 147456

// ---- kvstate kernel smem ----
#define KCH 128
#define KV_SV 34816                           // SK [128][136]h then SV [128][72]h
#define KV_TOTAL (34816 + 18432 + 2048)       // + slack for paired-ldsm overread

// ---- attn kernel smem (two overlapping phases) ----
#define APITCH 136
#define AT2_SA   0                 // phase1: A qsim [128][136] h
#define AT2_SBH  34816             // phase1: Bh [72][136] h
#define AT2_SBL  54400             // phase1: Bl [72][136] h (ends 73984)
#define AT2_SACC 0                 // phase2: f32 [128][77] = 39424
#define AT2_SVP  39424             // phase2: uint [128][33]
#define AT2_SG   56320             // phase2: uint [128][33]
#define AT2_AH   73216             // phase2: uint [128][33]
#define AT2_AL   90112             // phase2: uint [128][33]
#define AT2_TOTAL 107008

// ---------------- scratch (device globals; no allocations allowed) ----------
__device__ __half d_q[ROWS*CC];     // signed pow of q (fp16)
__device__ __half d_g[ROWS*CC];
__device__ __half d_k[ROWS*CC];     // signed pow of k (fp16)
__device__ __half d_v[ROWS*CC];
__device__ __half d_vpos[ROWS*CC];
__device__ float d_kvsum2[BB*HN*128*72];   // per bh: [128 ch_cat][72] (64 kv + ksum + pad)
__device__ float d_invscale[CC];
__device__ float d_pdelta[CC];      // power - 3
__device__ __half d_xhi[ROWS*CC];
__device__ __half d_xlo[ROWS*CC];
__device__ __half d_acthi[ROWS*CC];
__device__ __half d_actlo[ROWS*CC];
__device__ __half d_wqgt_h[2*CC*CC];
__device__ __half d_wqgt_l[2*CC*CC];
__device__ __half d_wkvt_h[2*CC*CC];
__device__ __half d_wkvt_l[2*CC*CC];
__device__ __half d_wpt_h[CC*CC];
__device__ __half d_wpt_l[CC*CC];

// ---------------- PTX helpers -------------------------------------------------
__device__ __forceinline__ uint32_t smem_u32(const void* p) {
    uint32_t a;
    asm("{ .reg .u64 t; cvta.to.shared.u64 t, %1; cvt.u32.u64 %0, t; }" : "=r"(a) : "l"(p));
    return a;
}

__device__ __forceinline__ void cp_async16(uint32_t dst, const void* src) {
    asm volatile("cp.async.cg.shared.global [%0], [%1], 16;" :: "r"(dst), "l"(src));
}
__device__ __forceinline__ void cp_commit() {
    asm volatile("cp.async.commit_group;");
}
template<int N>
__device__ __forceinline__ void cp_wait() {
    asm volatile("cp.async.wait_group %0;" :: "n"(N));
}

__device__ __forceinline__ void ldsm4(uint32_t addr, uint32_t& r0, uint32_t& r1,
                                      uint32_t& r2, uint32_t& r3) {
    asm volatile("ldmatrix.sync.aligned.m8n8.x4.shared.b16 {%0,%1,%2,%3}, [%4];"
                 : "=r"(r0), "=r"(r1), "=r"(r2), "=r"(r3) : "r"(addr));
}

__device__ __forceinline__ void ldsm4t(uint32_t addr, uint32_t& r0, uint32_t& r1,
                                       uint32_t& r2, uint32_t& r3) {
    asm volatile("ldmatrix.sync.aligned.m8n8.x4.trans.shared.b16 {%0,%1,%2,%3}, [%4];"
                 : "=r"(r0), "=r"(r1), "=r"(r2), "=r"(r3) : "r"(addr));
}

__device__ __forceinline__ void mma16816(float* c, const uint32_t* a, const uint32_t* b) {
    asm volatile(
        "mma.sync.aligned.m16n8k16.row.col.f32.f16.f16.f32 "
        "{%0,%1,%2,%3}, {%4,%5,%6,%7}, {%8,%9}, {%0,%1,%2,%3};"
        : "+f"(c[0]), "+f"(c[1]), "+f"(c[2]), "+f"(c[3])
        : "r"(a[0]), "r"(a[1]), "r"(a[2]), "r"(a[3]), "r"(b[0]), "r"(b[1]));
}

// ---------------- MUFU-free signed pow: sign(x)*|x|^(3+delta) ----------------
__device__ __forceinline__ float spow_fast(float x, float delta)
{
    float ax = fabsf(x);
    int i = __float_as_int(ax);
    int e = ((i >> 23) & 0xFF) - 127;
    float m = __int_as_float((i & 0x7FFFFF) | 0x3F800000);
    if (m > 1.41421356f) { m *= 0.5f; e += 1; }
    float t = m - 1.0f;
    float p = -0.125f;
    p = fmaf(p, t, 0.14285714f);
    p = fmaf(p, t, -0.16666667f);
    p = fmaf(p, t, 0.2f);
    p = fmaf(p, t, -0.25f);
    p = fmaf(p, t, 0.33333333f);
    p = fmaf(p, t, -0.5f);
    p = fmaf(p, t, 1.0f);
    float lnax = fmaf((float)e, 0.69314718f, t * p);
    float u = delta * lnax;
    float eu = fmaf(u, 0.04166667f, 0.16666667f);
    eu = fmaf(eu, u, 0.5f);
    eu = fmaf(eu, u, 1.0f);
    eu = fmaf(eu, u, 1.0f);
    float r = ax * ax * ax * eu;
    r = copysignf(r, x);
    return (ax > 0.f) ? r : 0.f;
}

// ---------------- params ------------------------------------------------------
__global__ void params_kernel(const float* __restrict__ scale_p,
                              const float* __restrict__ power_p)
{
    int c = threadIdx.x;
    if (c < CC) {
        float sp = scale_p[c];
        float sc = (sp > 20.f) ? sp : log1pf(__expf(sp));
        d_invscale[c] = 1.f / sc;
        float pp = power_p[c];
        d_pdelta[c] = 4.f / (1.f + __expf(-pp)) - 2.f;
    }
}

// ---------------- fp32 -> (hi,lo) fp16 split ---------------------------------
__device__ __forceinline__ void split2h(float v, uint32_t& hi, uint32_t& lo, int shift)
{
    __half h = __float2half(v);
    __half l = __float2half(v - __half2float(h));
    hi |= (uint32_t)__half_as_ushort(h) << shift;
    lo |= (uint32_t)__half_as_ushort(l) << shift;
}

__global__ void convert_split_kernel(const float* __restrict__ in,
                                     __half* __restrict__ hi,
                                     __half* __restrict__ lo)
{
    size_t i = ((size_t)blockIdx.x * blockDim.x + threadIdx.x) * 4;
    float4 v = *(const float4*)(in + i);
    uint32_t h0 = 0, l0 = 0, h1 = 0, l1 = 0;
    split2h(v.x, h0, l0, 0);  split2h(v.y, h0, l0, 16);
    split2h(v.z, h1, l1, 0);  split2h(v.w, h1, l1, 16);
    *(uint2*)(hi + i) = make_uint2(h0, h1);
    *(uint2*)(lo + i) = make_uint2(l0, l1);
}

// W [K=768, Nw] -> Wt split-fp16 [Nw, 768]
__global__ void wtrans_kernel(const float* __restrict__ W,
                              __half* __restrict__ hi,
                              __half* __restrict__ lo, int Nw)
{
    __shared__ float tile[32][33];
    int n0 = blockIdx.x * 32, k0 = blockIdx.y * 32;
    int tx = threadIdx.x, ty = threadIdx.y;
#pragma unroll
    for (int i = 0; i < 4; i++)
        tile[ty + i*8][tx] = W[(size_t)(k0 + ty + i*8) * Nw + n0 + tx];
    __syncthreads();
#pragma unroll
    for (int i = 0; i < 4; i++) {
        float v = tile[tx][ty + i*8];
        __half h = __float2half(v);
        __half l = __float2half(v - __half2float(h));
        size_t o = (size_t)(n0 + ty + i*8) * CC + k0 + tx;
        hi[o] = h; lo[o] = l;
    }
}

// ---------------- HMMA split-fp16 GEMM (unchanged from R8 best) ---------------
template<int MODE>
__global__ __launch_bounds__(256, 1)
void mma_gemm(const __half* __restrict__ Ah_g, const __half* __restrict__ Al_g,
              const __half* __restrict__ Bh_g, const __half* __restrict__ Bl_g,
              const float* __restrict__ aux0, const float* __restrict__ aux1,
              const float* __restrict__ pdelta,
              void* __restrict__ out0v, void* __restrict__ out1v)
{
    extern __shared__ char smem[];
    const int tid = threadIdx.x;
    const int rowBase = blockIdx.y * TM;
    const int colBase = blockIdx.x * TN;
    const bool third = (MODE != 2) && (colBase < CC);
    const uint32_t sbase = smem_u32(smem);

    const int lane = tid & 31;
    const int w = tid >> 5;
    const int m0 = (w >> 2) * 64;
    const int n0 = (w & 3) * 32;

    const __half* srcs[4] = { Ah_g, Al_g, Bh_g, Bl_g };

    float acc[4][4][4];
#pragma unroll
    for (int i = 0; i < 4; i++)
#pragma unroll
        for (int j = 0; j < 4; j++)
#pragma unroll
            for (int r = 0; r < 4; r++) acc[i][j][r] = 0.f;

    auto issue_loads = [&](int ch, int stage) {
        const int k0 = ch * KC;
        const uint32_t sb = sbase + stage * STAGE_BYTES;
#pragma unroll
        for (int it = 0; it < 16; ++it) {
            int id = it * 256 + tid;
            int which = id >> 10;
            if (which == 1 && !third) continue;
            int rem = id & 1023;
            int row = rem >> 3;
            int q = rem & 7;
            int grow = (which < 2) ? (rowBase + row) : (colBase + row);
            const __half* src = srcs[which] + (size_t)grow * CC + k0 + q * 8;
            cp_async16(sb + which * TILE_BYTES + row * ROWB + q * 16, src);
        }
        cp_commit();
    };

    issue_loads(0, 0);

    const int a_row = ((lane >> 3) & 1) * 8 + (lane & 7);
    const int a_koff = ((lane >> 4) & 1) * 8;
    const int b_row = ((lane >> 4) & 1) * 8 + (lane & 7);
    const int b_koff = ((lane >> 3) & 1) * 8;

    for (int ch = 0; ch < NCHUNK; ++ch) {
        const int stage = ch & 1;
        cp_wait<0>();
        __syncthreads();
        if (ch + 1 < NCHUNK)
            issue_loads(ch + 1, (ch + 1) & 1);

        const uint32_t sb = sbase + stage * STAGE_BYTES;
        const uint32_t sAh = sb;
        const uint32_t sAl = sb + TILE_BYTES;
        const uint32_t sBh = sb + 2 * TILE_BYTES;
        const uint32_t sBl = sb + 3 * TILE_BYTES;

#pragma unroll
        for (int k16 = 0; k16 < KC / 16; ++k16) {
            const int ko = k16 * 16;
            uint32_t ah[4][4], al[4][4], bh[2][4], bl[2][4];
#pragma unroll
            for (int mi = 0; mi < 4; ++mi) {
                uint32_t off = (uint32_t)((m0 + mi * 16 + a_row) * ROWB + (ko + a_koff) * 2);
                ldsm4(sAh + off, ah[mi][0], ah[mi][1], ah[mi][2], ah[mi][3]);
                if (third)
                    ldsm4(sAl + off, al[mi][0], al[mi][1], al[mi][2], al[mi][3]);
            }
#pragma unroll
            for (int j = 0; j < 2; ++j) {
                uint32_t off = (uint32_t)((n0 + j * 16 + b_row) * ROWB + (ko + b_koff) * 2);
                ldsm4(sBh + off, bh[j][0], bh[j][1], bh[j][2], bh[j][3]);
                ldsm4(sBl + off, bl[j][0], bl[j][1], bl[j][2], bl[j][3]);
            }
#pragma unroll
            for (int mi = 0; mi < 4; ++mi)
#pragma unroll
                for (int nt = 0; nt < 4; ++nt)
                    mma16816(acc[mi][nt], ah[mi], &bh[nt >> 1][(nt & 1) * 2]);
#pragma unroll
            for (int mi = 0; mi < 4; ++mi)
#pragma unroll
                for (int nt = 0; nt < 4; ++nt)
                    mma16816(acc[mi][nt], ah[mi], &bl[nt >> 1][(nt & 1) * 2]);
            if (third) {
#pragma unroll
                for (int mi = 0; mi < 4; ++mi)
#pragma unroll
                    for (int nt = 0; nt < 4; ++nt)
                        mma16816(acc[mi][nt], al[mi], &bh[nt >> 1][(nt & 1) * 2]);
            }
        }
        __syncthreads();
    }

    const int gid = lane >> 2, tig = lane & 3;
#pragma unroll
    for (int mi = 0; mi < 4; ++mi) {
#pragma unroll
        for (int nt = 0; nt < 4; ++nt) {
            int r0 = rowBase + m0 + mi * 16 + gid;
            int c = colBase + n0 + nt * 8 + tig * 2;
#pragma unroll
            for (int half = 0; half < 2; ++half) {
                int r = r0 + half * 8;
                float v0 = acc[mi][nt][half * 2 + 0];
                float v1 = acc[mi][nt][half * 2 + 1];
                if (MODE == 0) {
                    if (c < CC) {
                        float q0 = spow_fast(v0 * aux0[c],     pdelta[c]);
                        float q1 = spow_fast(v1 * aux0[c + 1], pdelta[c + 1]);
                        *(__half2*)((__half*)out0v + (size_t)r * CC + c) = __floats2half2_rn(q0, q1);
                    } else {
                        *(__half2*)((__half*)out1v + (size_t)r * CC + c - CC) = __floats2half2_rn(v0, v1);
                    }
                } else if (MODE == 1) {
                    if (c < CC) {
                        const float* pe = aux1 + (size_t)(r & (NN - 1)) * CC + c;
                        float k0v = spow_fast((v0 + pe[0]) * aux0[c],     pdelta[c]);
                        float k1v = spow_fast((v1 + pe[1]) * aux0[c + 1], pdelta[c + 1]);
                        *(__half2*)((__half*)out0v + (size_t)r * CC + c) = __floats2half2_rn(k0v, k1v);
                    } else {
                        *(__half2*)((__half*)out1v + (size_t)r * CC + c - CC) = __floats2half2_rn(v0, v1);
                    }
                } else {
                    float2 o = make_float2(v0 + aux0[c], v1 + aux0[c + 1]);
                    *(float2*)((float*)out0v + (size_t)r * CC + c) = o;
                }
            }
        }
    }
}

// ---------------- kv-state via HMMA: per bh  kcat^T[128x4096] @ [v|1] --------
__global__ __launch_bounds__(256)
void kvstate_kernel()
{
    extern __shared__ char sm[];
    __half* SK = (__half*)sm;                 // [KCH][136]
    __half* SV = (__half*)(sm + KV_SV);       // [KCH][72]
    const uint32_t sb = smem_u32(sm);

    const int bh = blockIdx.x;
    const int b = bh / HN, h = bh % HN;
    const int t = threadIdx.x;
    const int w = t >> 5, lane = t & 31;
    const int m0 = w * 16;

    if (t < KCH) {
        SV[t*72 + 64] = __float2half(1.f);
#pragma unroll
        for (int j = 65; j < 72; j++) SV[t*72 + j] = __float2half(0.f);
    }

    float acc[9][4];
#pragma unroll
    for (int nt = 0; nt < 9; nt++)
#pragma unroll
        for (int r = 0; r < 4; r++) acc[nt][r] = 0.f;

    const int a_tok = ((lane >> 4) & 1) * 8 + (lane & 7);
    const int a_moff = ((lane >> 3) & 1) * 8;
    const int b_tok = ((lane >> 3) & 1) * 8 + (lane & 7);
    const int b_noff = ((lane >> 4) & 1) * 8;
    const __half2 z2 = __floats2half2_rn(0.f, 0.f);

    for (int ch = 0; ch < NN / KCH; ++ch) {
#pragma unroll
        for (int i = 0; i < (KCH*32)/256; ++i) {
            int idx = i * 256 + t;
            int r = idx >> 5, ul = idx & 31;
            size_t base = ((size_t)(b*NN + ch*KCH + r))*CC + h*64;
            uint32_t ku = ((const uint32_t*)(d_k + base))[ul];
            uint32_t vu = ((const uint32_t*)(d_v + base))[ul];
            __half2 k2 = *(__half2*)&ku;
            __half2 kp = __hmax2(k2, z2);
            __half2 kn = __hmax2(__hneg2(k2), z2);
            ((uint32_t*)(SK + r*136))[ul]      = *(uint32_t*)&kp;
            ((uint32_t*)(SK + r*136 + 64))[ul] = *(uint32_t*)&kn;
            ((uint32_t*)(SV + r*72))[ul]       = vu;
        }
        __syncthreads();
#pragma unroll
        for (int k16 = 0; k16 < KCH/16; ++k16) {
            const int ko = k16 * 16;
            uint32_t a[4];
            ldsm4t(sb + (uint32_t)(((ko + a_tok)*136 + m0 + a_moff)*2),
                   a[0], a[1], a[2], a[3]);
            uint32_t bf[5][4];
#pragma unroll
            for (int s = 0; s < 5; ++s)
                ldsm4t(sb + KV_SV + (uint32_t)(((ko + b_tok)*72 + s*16 + b_noff)*2),
                       bf[s][0], bf[s][1], bf[s][2], bf[s][3]);
#pragma unroll
            for (int nt = 0; nt < 9; ++nt)
                mma16816(acc[nt], a, &bf[nt >> 1][(nt & 1) * 2]);
        }
        __syncthreads();
    }

    const int gid = lane >> 2, tig = lane & 3;
    float* outp = d_kvsum2 + (size_t)bh * 128 * 72;
#pragma unroll
    for (int nt = 0; nt < 9; ++nt) {
        int c0 = nt * 8 + tig * 2;
        outp[(m0 + gid)*72 + c0]     = acc[nt][0];
        outp[(m0 + gid)*72 + c0 + 1] = acc[nt][1];
        outp[(m0 + 8 + gid)*72 + c0]     = acc[nt][2];
        outp[(m0 + 8 + gid)*72 + c0 + 1] = acc[nt][3];
    }
}

// ---------------- attn via HMMA: qsim[128x128] @ B[128x72] + fused epilogue ---
__global__ __launch_bounds__(256)
void attn_kernel()
{
    extern __shared__ char sm[];
    __half* SA  = (__half*)(sm + AT2_SA);
    __half* SBH = (__half*)(sm + AT2_SBH);
    __half* SBL = (__half*)(sm + AT2_SBL);
    const uint32_t sb = smem_u32(sm);

    const int bh = blockIdx.y;
    const int b = bh / HN, h = bh % HN;
    const int ntile = blockIdx.x;
    const int t = threadIdx.x;
    const int w = t >> 5, lane = t & 31;
    const int m0 = w * 16;
    const size_t blkbase = ((size_t)(b*NN + ntile*128))*CC + h*64;
    const float invn = 1.f / (float)NN;
    const __half2 z2 = __floats2half2_rn(0.f, 0.f);

    // build A = q_sim [128 r][128 ch] (pos | neg), exact from fp16 q
#pragma unroll
    for (int i = 0; i < 16; ++i) {
        int idx = i * 256 + t;
        int r = idx >> 5, ul = idx & 31;
        uint32_t qu = ((const uint32_t*)(d_q + blkbase + (size_t)r*CC))[ul];
        __half2 q2 = *(__half2*)&qu;
        __half2 qp = __hmax2(q2, z2);
        __half2 qn = __hmax2(__hneg2(q2), z2);
        ((uint32_t*)(SA + r*APITCH))[ul]      = *(uint32_t*)&qp;
        ((uint32_t*)(SA + r*APITCH + 64))[ul] = *(uint32_t*)&qn;
    }
    // build B [72 n][128 k], 2-term split, inv_n folded
    const float* kvb = d_kvsum2 + (size_t)bh * 128 * 72;
    for (int idx = t; idx < 72*128; idx += 256) {
        int n = idx >> 7, k = idx & 127;
        int srcrow = ((n >= 32 && n < 64) || n == 65) ? ((k + 64) & 127) : k;
        int srccol = (n < 64) ? n : 64;
        float f = (n < 66) ? kvb[srcrow*72 + srccol] * invn : 0.f;
        __half hh = __float2half(f);
        SBH[n*APITCH + k] = hh;
        SBL[n*APITCH + k] = __float2half(f - __half2float(hh));
    }
    __syncthreads();

    float acc[9][4];
#pragma unroll
    for (int nt = 0; nt < 9; nt++)
#pragma unroll
        for (int r = 0; r < 4; r++) acc[nt][r] = 0.f;

    const int a_row = ((lane >> 3) & 1) * 8 + (lane & 7);
    const int a_koff = ((lane >> 4) & 1) * 8;
    const int b_row = ((lane >> 4) & 1) * 8 + (lane & 7);
    const int b_koff = ((lane >> 3) & 1) * 8;

#pragma unroll
    for (int k16 = 0; k16 < 8; ++k16) {
        const int ko = k16 * 16;
        uint32_t a[4];
        ldsm4(sb + AT2_SA + (uint32_t)(((m0 + a_row)*APITCH + ko + a_koff)*2),
              a[0], a[1], a[2], a[3]);
        uint32_t bhf[5][4], blf[5][4];
#pragma unroll
        for (int s = 0; s < 5; ++s) {
            uint32_t off = (uint32_t)(((s*16 + b_row)*APITCH + ko + b_koff)*2);
            ldsm4(sb + AT2_SBH + off, bhf[s][0], bhf[s][1], bhf[s][2], bhf[s][3]);
            ldsm4(sb + AT2_SBL + off, blf[s][0], blf[s][1], blf[s][2], blf[s][3]);
        }
#pragma unroll
        for (int nt = 0; nt < 9; ++nt)
            mma16816(acc[nt], a, &bhf[nt >> 1][(nt & 1) * 2]);
#pragma unroll
        for (int nt = 0; nt < 9; ++nt)
            mma16816(acc[nt], a, &blf[nt >> 1][(nt & 1) * 2]);
    }
    __syncthreads();

    // phase 2: accumulators -> smem, stage vpos/g, fused epilogue
    float* SACC = (float*)(sm + AT2_SACC);
    uint32_t* SVP = (uint32_t*)(sm + AT2_SVP);
    uint32_t* SG  = (uint32_t*)(sm + AT2_SG);
    uint32_t* AH  = (uint32_t*)(sm + AT2_AH);
    uint32_t* AL  = (uint32_t*)(sm + AT2_AL);

    const int gid = lane >> 2, tig = lane & 3;
#pragma unroll
    for (int nt = 0; nt < 9; ++nt) {
        int c0 = nt * 8 + tig * 2;
        SACC[(m0 + gid)*77 + c0]     = acc[nt][0];
        SACC[(m0 + gid)*77 + c0 + 1] = acc[nt][1];
        SACC[(m0 + 8 + gid)*77 + c0]     = acc[nt][2];
        SACC[(m0 + 8 + gid)*77 + c0 + 1] = acc[nt][3];
    }
#pragma unroll
    for (int i = 0; i < 16; ++i) {
        int idx = i * 256 + t;
        int r = idx >> 5, ul = idx & 31;
        SVP[r*33 + ul] = ((const uint32_t*)(d_vpos + blkbase + (size_t)r*CC))[ul];
        SG [r*33 + ul] = ((const uint32_t*)(d_g    + blkbase + (size_t)r*CC))[ul];
    }
    __syncthreads();

    {
        const int r = t & 127;
        const int chalf = t >> 7;               // 0: cols 0-31 (sim), 1: 32-63 (opp)
        float den = SACC[r*77 + 64 + chalf];
        float z = 1.f / (den + EPSV);
#pragma unroll
        for (int c4 = 0; c4 < 8; ++c4) {
            int c = chalf*32 + c4*4;
            float a0 = SACC[r*77 + c + 0] * z;
            float a1 = SACC[r*77 + c + 1] * z;
            float a2 = SACC[r*77 + c + 2] * z;
            float a3 = SACC[r*77 + c + 3] * z;
            uint32_t vu0 = SVP[r*33 + (c>>1)], vu1 = SVP[r*33 + (c>>1) + 1];
            uint32_t gu0 = SG [r*33 + (c>>1)], gu1 = SG [r*33 + (c>>1) + 1];
            float2 va = __half22float2(*(__half2*)&vu0);
            float2 vb = __half22float2(*(__half2*)&vu1);
            float2 ga = __half22float2(*(__half2*)&gu0);
            float2 gb = __half22float2(*(__half2*)&gu1);
            float r0 = (a0 + va.x) * ga.x;
            float r1 = (a1 + va.y) * ga.y;
            float r2 = (a2 + vb.x) * gb.x;
            float r3 = (a3 + vb.y) * gb.y;
            uint32_t h0 = 0, l0 = 0, h1 = 0, l1 = 0;
            split2h(r0, h0, l0, 0);  split2h(r1, h0, l0, 16);
            split2h(r2, h1, l1, 0);  split2h(r3, h1, l1, 16);
            AH[r*33 + (c>>1)]     = h0;
            AH[r*33 + (c>>1) + 1] = h1;
            AL[r*33 + (c>>1)]     = l0;
            AL[r*33 + (c>>1) + 1] = l1;
        }
    }
    __syncthreads();

#pragma unroll
    for (int rr = 0; rr < 16; ++rr) {
        int r = w * 16 + rr;
        ((uint32_t*)(d_acthi + blkbase + (size_t)r*CC))[lane] = AH[r*33 + lane];
        ((uint32_t*)(d_actlo + blkbase + (size_t)r*CC))[lane] = AL[r*33 + lane];
    }
}

// ---------------- depthwise conv (fp16 in/out) --------------------------------
__global__ void dwconv_kernel(const float* __restrict__ w,
                              const float* __restrict__ bias)
{
    const int bh = blockIdx.z;
    const int b = bh / HN, h = bh % HN;
    const int y = blockIdx.y;
    const int x = blockIdx.x * 4 + threadIdx.y;
    const int d = threadIdx.x;

    float wr[25];
#pragma unroll
    for (int i = 0; i < 25; i++) wr[i] = __ldg(&w[d*25 + i]);

    float acc = bias[d];
#pragma unroll
    for (int dy = 0; dy < 5; dy++) {
        int yy = y + dy - 2;
        if (yy < 0 || yy >= 64) continue;
#pragma unroll
        for (int dx = 0; dx < 5; dx++) {
            int xx = x + dx - 2;
            if (xx < 0 || xx >= 64) continue;
            acc += wr[dy*5 + dx] *
                   __half2float(d_v[((size_t)(b*NN + yy*64 + xx))*CC + h*64 + d]);
        }
    }
    d_vpos[((size_t)(b*NN + y*64 + x))*CC + h*64 + d] = __float2half(acc);
}

// ---------------- launcher ----------------------------------------------------
extern "C" void kernel_launch(void* const* d_in, const int* in_sizes, int n_in,
                              void* d_out, int out_size)
{
    const float* x       = (const float*)d_in[0];
    const float* Wqg     = (const float*)d_in[1];
    const float* Wkv     = (const float*)d_in[2];
    const float* Wproj   = (const float*)d_in[3];
    const float* bproj   = (const float*)d_in[4];
    const float* dwc_w   = (const float*)d_in[5];
    const float* dwc_b   = (const float*)d_in[6];
    const float* power_p = (const float*)d_in[7];
    const float* scale_p = (const float*)d_in[8];
    const float* pos_enc = (const float*)d_in[9];
    float* out = (float*)d_out;

    float *pis, *ppd;
    __half *pq, *pg, *pk, *pv;
    __half *pxh, *pxl, *pah, *pal;
    __half *pqgh, *pqgl, *pkvh, *pkvl, *pph, *ppl;
    cudaGetSymbolAddress((void**)&pq,  d_q);
    cudaGetSymbolAddress((void**)&pg,  d_g);
    cudaGetSymbolAddress((void**)&pk,  d_k);
    cudaGetSymbolAddress((void**)&pv,  d_v);
    cudaGetSymbolAddress((void**)&pis, d_invscale);
    cudaGetSymbolAddress((void**)&ppd, d_pdelta);
    cudaGetSymbolAddress((void**)&pxh, d_xhi);
    cudaGetSymbolAddress((void**)&pxl, d_xlo);
    cudaGetSymbolAddress((void**)&pah, d_acthi);
    cudaGetSymbolAddress((void**)&pal, d_actlo);
    cudaGetSymbolAddress((void**)&pqgh, d_wqgt_h);
    cudaGetSymbolAddress((void**)&pqgl, d_wqgt_l);
    cudaGetSymbolAddress((void**)&pkvh, d_wkvt_h);
    cudaGetSymbolAddress((void**)&pkvl, d_wkvt_l);
    cudaGetSymbolAddress((void**)&pph, d_wpt_h);
    cudaGetSymbolAddress((void**)&ppl, d_wpt_l);

    cudaFuncSetAttribute(mma_gemm<0>, cudaFuncAttributeMaxDynamicSharedMemorySize, SM_TOTAL);
    cudaFuncSetAttribute(mma_gemm<1>, cudaFuncAttributeMaxDynamicSharedMemorySize, SM_TOTAL);
    cudaFuncSetAttribute(mma_gemm<2>, cudaFuncAttributeMaxDynamicSharedMemorySize, SM_TOTAL);
    cudaFuncSetAttribute(kvstate_kernel, cudaFuncAttributeMaxDynamicSharedMemorySize, KV_TOTAL);
    cudaFuncSetAttribute(attn_kernel, cudaFuncAttributeMaxDynamicSharedMemorySize, AT2_TOTAL);

    params_kernel<<<1, CC>>>(scale_p, power_p);

    convert_split_kernel<<<(ROWS*CC/4)/256, 256>>>(x, pxh, pxl);
    wtrans_kernel<<<dim3(2*CC/32, CC/32), dim3(32, 8)>>>(Wqg, pqgh, pqgl, 2*CC);
    wtrans_kernel<<<dim3(2*CC/32, CC/32), dim3(32, 8)>>>(Wkv, pkvh, pkvl, 2*CC);
    wtrans_kernel<<<dim3(CC/32,   CC/32), dim3(32, 8)>>>(Wproj, pph, ppl, CC);

    // qg = x @ Wqg (q: 3-term + scaled pow epilogue; g: 2-term)
    mma_gemm<0><<<dim3(2*CC/TN, ROWS/TM), 256, SM_TOTAL>>>(
        pxh, pxl, pqgh, pqgl, pis, nullptr, ppd, pq, pg);
    // kv = x @ Wkv (k: 3-term + pos_enc/scale/pow epilogue; v: 2-term)
    mma_gemm<1><<<dim3(2*CC/TN, ROWS/TM), 256, SM_TOTAL>>>(
        pxh, pxl, pkvh, pkvl, pis, pos_enc, ppd, pk, pv);

    kvstate_kernel<<<BB*HN, 256, KV_TOTAL>>>();
    dwconv_kernel<<<dim3(16, 64, BB*HN), dim3(64, 4)>>>(dwc_w, dwc_b);
    attn_kernel<<<dim3(NN/128, BB*HN), 256, AT2_TOTAL>>>();

    // out = act @ Wproj + bproj (2-term)
    mma_gemm<2><<<dim3(CC/TN, ROWS/TM), 256, SM_TOTAL>>>(
        pah, pal, pph, ppl, bproj, nullptr, nullptr, out, nullptr);
}

// round 14
// speedup vs baseline: 1.0017x; 1.0017x over previous
#include <cuda_runtime.h>
#include <cuda_fp16.h>
#include <math.h>
#include <cstdint>

#define BB 8
#define NN 4096
#define CC 768
#define HN 12
#define HD 64
#define ROWS (BB*NN)
#define EPSV 1e-6f

// ---- HMMA GEMM tiling ----
#define TM 128
#define TN 128
#define KC 64
#define NCHUNK (CC/KC)             // 12
#define ROWB 144                   // padded smem row stride (bytes) for 64 fp16
#define TILE_BYTES (128*ROWB)      // 18432
#define STAGE_BYTES (4*TILE_BYTES) // Ah,Al,Bh,Bl = 73728
#define SM_TOTAL (2*STAGE_BYTES)   // 147456

// ---- kvstate kernel smem ----
#define KCH 128
#define KV_SV 34816                           // SK [128][136]h then SV [128][72]h
#define KV_TOTAL (34816 + 18432 + 2048)       // + slack for paired-ldsm overread

// ---- attn kernel smem (two overlapping phases) ----
#define APITCH 136
#define AT2_SA   0                 // phase1: A qsim [128][136] h
#define AT2_SBH  34816             // phase1: Bh [72][136] h
#define AT2_SBL  54400             // phase1: Bl [72][136] h (ends 73984)
#define AT2_SACC 0                 // phase2: f32 [128][77] = 39424
#define AT2_SVP  39424             // phase2: uint [128][33]
#define AT2_SG   56320             // phase2: uint [128][33]
#define AT2_AH   73216             // phase2: uint [128][33]
#define AT2_AL   90112             // phase2: uint [128][33]
#define AT2_TOTAL 107008

// ---------------- scratch (device globals; no allocations allowed) ----------
__device__ __half d_q[ROWS*CC];     // signed pow of q (fp16)
__device__ __half d_g[ROWS*CC];
__device__ __half d_k[ROWS*CC];     // signed pow of k (fp16)
__device__ __half d_v[ROWS*CC];
__device__ __half d_vpos[ROWS*CC];
__device__ float d_kvsum2[BB*HN*128*72];   // per bh: [128 ch_cat][72] (64 kv + ksum + pad)
__device__ float d_invscale[CC];
__device__ float d_pdelta[CC];      // power - 3
__device__ __half d_xhi[ROWS*CC];
__device__ __half d_xlo[ROWS*CC];
__device__ __half d_acthi[ROWS*CC];
__device__ __half d_actlo[ROWS*CC];
__device__ __half d_wqgt_h[2*CC*CC];
__device__ __half d_wqgt_l[2*CC*CC];
__device__ __half d_wkvt_h[2*CC*CC];
__device__ __half d_wkvt_l[2*CC*CC];
__device__ __half d_wpt_h[CC*CC];
__device__ __half d_wpt_l[CC*CC];

// ---------------- PTX helpers -------------------------------------------------
__device__ __forceinline__ uint32_t smem_u32(const void* p) {
    uint32_t a;
    asm("{ .reg .u64 t; cvta.to.shared.u64 t, %1; cvt.u32.u64 %0, t; }" : "=r"(a) : "l"(p));
    return a;
}

__device__ __forceinline__ void cp_async16(uint32_t dst, const void* src) {
    asm volatile("cp.async.cg.shared.global [%0], [%1], 16;" :: "r"(dst), "l"(src));
}
__device__ __forceinline__ void cp_commit() {
    asm volatile("cp.async.commit_group;");
}
template<int N>
__device__ __forceinline__ void cp_wait() {
    asm volatile("cp.async.wait_group %0;" :: "n"(N));
}

__device__ __forceinline__ void ldsm4(uint32_t addr, uint32_t& r0, uint32_t& r1,
                                      uint32_t& r2, uint32_t& r3) {
    asm volatile("ldmatrix.sync.aligned.m8n8.x4.shared.b16 {%0,%1,%2,%3}, [%4];"
                 : "=r"(r0), "=r"(r1), "=r"(r2), "=r"(r3) : "r"(addr));
}

__device__ __forceinline__ void ldsm4t(uint32_t addr, uint32_t& r0, uint32_t& r1,
                                       uint32_t& r2, uint32_t& r3) {
    asm volatile("ldmatrix.sync.aligned.m8n8.x4.trans.shared.b16 {%0,%1,%2,%3}, [%4];"
                 : "=r"(r0), "=r"(r1), "=r"(r2), "=r"(r3) : "r"(addr));
}

__device__ __forceinline__ void mma16816(float* c, const uint32_t* a, const uint32_t* b) {
    asm volatile(
        "mma.sync.aligned.m16n8k16.row.col.f32.f16.f16.f32 "
        "{%0,%1,%2,%3}, {%4,%5,%6,%7}, {%8,%9}, {%0,%1,%2,%3};"
        : "+f"(c[0]), "+f"(c[1]), "+f"(c[2]), "+f"(c[3])
        : "r"(a[0]), "r"(a[1]), "r"(a[2]), "r"(a[3]), "r"(b[0]), "r"(b[1]));
}

// ---------------- MUFU-free signed pow: sign(x)*|x|^(3+delta) ----------------
__device__ __forceinline__ float spow_fast(float x, float delta)
{
    float ax = fabsf(x);
    int i = __float_as_int(ax);
    int e = ((i >> 23) & 0xFF) - 127;
    float m = __int_as_float((i & 0x7FFFFF) | 0x3F800000);
    if (m > 1.41421356f) { m *= 0.5f; e += 1; }
    float t = m - 1.0f;
    float p = -0.125f;
    p = fmaf(p, t, 0.14285714f);
    p = fmaf(p, t, -0.16666667f);
    p = fmaf(p, t, 0.2f);
    p = fmaf(p, t, -0.25f);
    p = fmaf(p, t, 0.33333333f);
    p = fmaf(p, t, -0.5f);
    p = fmaf(p, t, 1.0f);
    float lnax = fmaf((float)e, 0.69314718f, t * p);
    float u = delta * lnax;
    float eu = fmaf(u, 0.04166667f, 0.16666667f);
    eu = fmaf(eu, u, 0.5f);
    eu = fmaf(eu, u, 1.0f);
    eu = fmaf(eu, u, 1.0f);
    float r = ax * ax * ax * eu;
    r = copysignf(r, x);
    return (ax > 0.f) ? r : 0.f;
}

// ---------------- params ------------------------------------------------------
__global__ void params_kernel(const float* __restrict__ scale_p,
                              const float* __restrict__ power_p)
{
    int c = threadIdx.x;
    if (c < CC) {
        float sp = scale_p[c];
        float sc = (sp > 20.f) ? sp : log1pf(__expf(sp));
        d_invscale[c] = 1.f / sc;
        float pp = power_p[c];
        d_pdelta[c] = 4.f / (1.f + __expf(-pp)) - 2.f;
    }
}

// ---------------- fp32 -> (hi,lo) fp16 split ---------------------------------
__device__ __forceinline__ void split2h(float v, uint32_t& hi, uint32_t& lo, int shift)
{
    __half h = __float2half(v);
    __half l = __float2half(v - __half2float(h));
    hi |= (uint32_t)__half_as_ushort(h) << shift;
    lo |= (uint32_t)__half_as_ushort(l) << shift;
}

__global__ void convert_split_kernel(const float* __restrict__ in,
                                     __half* __restrict__ hi,
                                     __half* __restrict__ lo)
{
    size_t i = ((size_t)blockIdx.x * blockDim.x + threadIdx.x) * 4;
    float4 v = *(const float4*)(in + i);
    uint32_t h0 = 0, l0 = 0, h1 = 0, l1 = 0;
    split2h(v.x, h0, l0, 0);  split2h(v.y, h0, l0, 16);
    split2h(v.z, h1, l1, 0);  split2h(v.w, h1, l1, 16);
    *(uint2*)(hi + i) = make_uint2(h0, h1);
    *(uint2*)(lo + i) = make_uint2(l0, l1);
}

// W [K=768, Nw] -> Wt split-fp16 [Nw, 768]
__global__ void wtrans_kernel(const float* __restrict__ W,
                              __half* __restrict__ hi,
                              __half* __restrict__ lo, int Nw)
{
    __shared__ float tile[32][33];
    int n0 = blockIdx.x * 32, k0 = blockIdx.y * 32;
    int tx = threadIdx.x, ty = threadIdx.y;
#pragma unroll
    for (int i = 0; i < 4; i++)
        tile[ty + i*8][tx] = W[(size_t)(k0 + ty + i*8) * Nw + n0 + tx];
    __syncthreads();
#pragma unroll
    for (int i = 0; i < 4; i++) {
        float v = tile[tx][ty + i*8];
        __half h = __float2half(v);
        __half l = __float2half(v - __half2float(h));
        size_t o = (size_t)(n0 + ty + i*8) * CC + k0 + tx;
        hi[o] = h; lo[o] = l;
    }
}

// ---------------- HMMA split-fp16 GEMM (unchanged from R8 best) ---------------
template<int MODE>
__global__ __launch_bounds__(256, 1)
void mma_gemm(const __half* __restrict__ Ah_g, const __half* __restrict__ Al_g,
              const __half* __restrict__ Bh_g, const __half* __restrict__ Bl_g,
              const float* __restrict__ aux0, const float* __restrict__ aux1,
              const float* __restrict__ pdelta,
              void* __restrict__ out0v, void* __restrict__ out1v)
{
    extern __shared__ char smem[];
    const int tid = threadIdx.x;
    const int rowBase = blockIdx.y * TM;
    const int colBase = blockIdx.x * TN;
    const bool third = (MODE != 2) && (colBase < CC);
    const uint32_t sbase = smem_u32(smem);

    const int lane = tid & 31;
    const int w = tid >> 5;
    const int m0 = (w >> 2) * 64;
    const int n0 = (w & 3) * 32;

    const __half* srcs[4] = { Ah_g, Al_g, Bh_g, Bl_g };

    float acc[4][4][4];
#pragma unroll
    for (int i = 0; i < 4; i++)
#pragma unroll
        for (int j = 0; j < 4; j++)
#pragma unroll
            for (int r = 0; r < 4; r++) acc[i][j][r] = 0.f;

    auto issue_loads = [&](int ch, int stage) {
        const int k0 = ch * KC;
        const uint32_t sb = sbase + stage * STAGE_BYTES;
#pragma unroll
        for (int it = 0; it < 16; ++it) {
            int id = it * 256 + tid;
            int which = id >> 10;
            if (which == 1 && !third) continue;
            int rem = id & 1023;
            int row = rem >> 3;
            int q = rem & 7;
            int grow = (which < 2) ? (rowBase + row) : (colBase + row);
            const __half* src = srcs[which] + (size_t)grow * CC + k0 + q * 8;
            cp_async16(sb + which * TILE_BYTES + row * ROWB + q * 16, src);
        }
        cp_commit();
    };

    issue_loads(0, 0);

    const int a_row = ((lane >> 3) & 1) * 8 + (lane & 7);
    const int a_koff = ((lane >> 4) & 1) * 8;
    const int b_row = ((lane >> 4) & 1) * 8 + (lane & 7);
    const int b_koff = ((lane >> 3) & 1) * 8;

    for (int ch = 0; ch < NCHUNK; ++ch) {
        const int stage = ch & 1;
        cp_wait<0>();
        __syncthreads();
        if (ch + 1 < NCHUNK)
            issue_loads(ch + 1, (ch + 1) & 1);

        const uint32_t sb = sbase + stage * STAGE_BYTES;
        const uint32_t sAh = sb;
        const uint32_t sAl = sb + TILE_BYTES;
        const uint32_t sBh = sb + 2 * TILE_BYTES;
        const uint32_t sBl = sb + 3 * TILE_BYTES;

#pragma unroll
        for (int k16 = 0; k16 < KC / 16; ++k16) {
            const int ko = k16 * 16;
            uint32_t ah[4][4], al[4][4], bh[2][4], bl[2][4];
#pragma unroll
            for (int mi = 0; mi < 4; ++mi) {
                uint32_t off = (uint32_t)((m0 + mi * 16 + a_row) * ROWB + (ko + a_koff) * 2);
                ldsm4(sAh + off, ah[mi][0], ah[mi][1], ah[mi][2], ah[mi][3]);
                if (third)
                    ldsm4(sAl + off, al[mi][0], al[mi][1], al[mi][2], al[mi][3]);
            }
#pragma unroll
            for (int j = 0; j < 2; ++j) {
                uint32_t off = (uint32_t)((n0 + j * 16 + b_row) * ROWB + (ko + b_koff) * 2);
                ldsm4(sBh + off, bh[j][0], bh[j][1], bh[j][2], bh[j][3]);
                ldsm4(sBl + off, bl[j][0], bl[j][1], bl[j][2], bl[j][3]);
            }
#pragma unroll
            for (int mi = 0; mi < 4; ++mi)
#pragma unroll
                for (int nt = 0; nt < 4; ++nt)
                    mma16816(acc[mi][nt], ah[mi], &bh[nt >> 1][(nt & 1) * 2]);
#pragma unroll
            for (int mi = 0; mi < 4; ++mi)
#pragma unroll
                for (int nt = 0; nt < 4; ++nt)
                    mma16816(acc[mi][nt], ah[mi], &bl[nt >> 1][(nt & 1) * 2]);
            if (third) {
#pragma unroll
                for (int mi = 0; mi < 4; ++mi)
#pragma unroll
                    for (int nt = 0; nt < 4; ++nt)
                        mma16816(acc[mi][nt], al[mi], &bh[nt >> 1][(nt & 1) * 2]);
            }
        }
        __syncthreads();
    }

    const int gid = lane >> 2, tig = lane & 3;
#pragma unroll
    for (int mi = 0; mi < 4; ++mi) {
#pragma unroll
        for (int nt = 0; nt < 4; ++nt) {
            int r0 = rowBase + m0 + mi * 16 + gid;
            int c = colBase + n0 + nt * 8 + tig * 2;
#pragma unroll
            for (int half = 0; half < 2; ++half) {
                int r = r0 + half * 8;
                float v0 = acc[mi][nt][half * 2 + 0];
                float v1 = acc[mi][nt][half * 2 + 1];
                if (MODE == 0) {
                    if (c < CC) {
                        float q0 = spow_fast(v0 * aux0[c],     pdelta[c]);
                        float q1 = spow_fast(v1 * aux0[c + 1], pdelta[c + 1]);
                        *(__half2*)((__half*)out0v + (size_t)r * CC + c) = __floats2half2_rn(q0, q1);
                    } else {
                        *(__half2*)((__half*)out1v + (size_t)r * CC + c - CC) = __floats2half2_rn(v0, v1);
                    }
                } else if (MODE == 1) {
                    if (c < CC) {
                        const float* pe = aux1 + (size_t)(r & (NN - 1)) * CC + c;
                        float k0v = spow_fast((v0 + pe[0]) * aux0[c],     pdelta[c]);
                        float k1v = spow_fast((v1 + pe[1]) * aux0[c + 1], pdelta[c + 1]);
                        *(__half2*)((__half*)out0v + (size_t)r * CC + c) = __floats2half2_rn(k0v, k1v);
                    } else {
                        *(__half2*)((__half*)out1v + (size_t)r * CC + c - CC) = __floats2half2_rn(v0, v1);
                    }
                } else {
                    float2 o = make_float2(v0 + aux0[c], v1 + aux0[c + 1]);
                    *(float2*)((float*)out0v + (size_t)r * CC + c) = o;
                }
            }
        }
    }
}

// ---------------- kv-state via HMMA: per bh  kcat^T[128x4096] @ [v|1] --------
__global__ __launch_bounds__(256)
void kvstate_kernel()
{
    extern __shared__ char sm[];
    __half* SK = (__half*)sm;                 // [KCH][136]
    __half* SV = (__half*)(sm + KV_SV);       // [KCH][72]
    const uint32_t sb = smem_u32(sm);

    const int bh = blockIdx.x;
    const int b = bh / HN, h = bh % HN;
    const int t = threadIdx.x;
    const int w = t >> 5, lane = t & 31;
    const int m0 = w * 16;

    if (t < KCH) {
        SV[t*72 + 64] = __float2half(1.f);
#pragma unroll
        for (int j = 65; j < 72; j++) SV[t*72 + j] = __float2half(0.f);
    }

    float acc[9][4];
#pragma unroll
    for (int nt = 0; nt < 9; nt++)
#pragma unroll
        for (int r = 0; r < 4; r++) acc[nt][r] = 0.f;

    const int a_tok = ((lane >> 4) & 1) * 8 + (lane & 7);
    const int a_moff = ((lane >> 3) & 1) * 8;
    const int b_tok = ((lane >> 3) & 1) * 8 + (lane & 7);
    const int b_noff = ((lane >> 4) & 1) * 8;
    const __half2 z2 = __floats2half2_rn(0.f, 0.f);

    for (int ch = 0; ch < NN / KCH; ++ch) {
#pragma unroll
        for (int i = 0; i < (KCH*32)/256; ++i) {
            int idx = i * 256 + t;
            int r = idx >> 5, ul = idx & 31;
            size_t base = ((size_t)(b*NN + ch*KCH + r))*CC + h*64;
            uint32_t ku = ((const uint32_t*)(d_k + base))[ul];
            uint32_t vu = ((const uint32_t*)(d_v + base))[ul];
            __half2 k2 = *(__half2*)&ku;
            __half2 kp = __hmax2(k2, z2);
            __half2 kn = __hmax2(__hneg2(k2), z2);
            ((uint32_t*)(SK + r*136))[ul]      = *(uint32_t*)&kp;
            ((uint32_t*)(SK + r*136 + 64))[ul] = *(uint32_t*)&kn;
            ((uint32_t*)(SV + r*72))[ul]       = vu;
        }
        __syncthreads();
#pragma unroll
        for (int k16 = 0; k16 < KCH/16; ++k16) {
            const int ko = k16 * 16;
            uint32_t a[4];
            ldsm4t(sb + (uint32_t)(((ko + a_tok)*136 + m0 + a_moff)*2),
                   a[0], a[1], a[2], a[3]);
            uint32_t bf[5][4];
#pragma unroll
            for (int s = 0; s < 5; ++s)
                ldsm4t(sb + KV_SV + (uint32_t)(((ko + b_tok)*72 + s*16 + b_noff)*2),
                       bf[s][0], bf[s][1], bf[s][2], bf[s][3]);
#pragma unroll
            for (int nt = 0; nt < 9; ++nt)
                mma16816(acc[nt], a, &bf[nt >> 1][(nt & 1) * 2]);
        }
        __syncthreads();
    }

    const int gid = lane >> 2, tig = lane & 3;
    float* outp = d_kvsum2 + (size_t)bh * 128 * 72;
#pragma unroll
    for (int nt = 0; nt < 9; ++nt) {
        int c0 = nt * 8 + tig * 2;
        outp[(m0 + gid)*72 + c0]     = acc[nt][0];
        outp[(m0 + gid)*72 + c0 + 1] = acc[nt][1];
        outp[(m0 + 8 + gid)*72 + c0]     = acc[nt][2];
        outp[(m0 + 8 + gid)*72 + c0 + 1] = acc[nt][3];
    }
}

// ---------------- attn via HMMA: qsim[128x128] @ B[128x72] + fused epilogue ---
__global__ __launch_bounds__(256)
void attn_kernel()
{
    extern __shared__ char sm[];
    __half* SA  = (__half*)(sm + AT2_SA);
    __half* SBH = (__half*)(sm + AT2_SBH);
    __half* SBL = (__half*)(sm + AT2_SBL);
    const uint32_t sb = smem_u32(sm);

    const int bh = blockIdx.y;
    const int b = bh / HN, h = bh % HN;
    const int ntile = blockIdx.x;
    const int t = threadIdx.x;
    const int w = t >> 5, lane = t & 31;
    const int m0 = w * 16;
    const size_t blkbase = ((size_t)(b*NN + ntile*128))*CC + h*64;
    const float invn = 1.f / (float)NN;
    const __half2 z2 = __floats2half2_rn(0.f, 0.f);

    // build A = q_sim [128 r][128 ch] (pos | neg), exact from fp16 q
#pragma unroll
    for (int i = 0; i < 16; ++i) {
        int idx = i * 256 + t;
        int r = idx >> 5, ul = idx & 31;
        uint32_t qu = ((const uint32_t*)(d_q + blkbase + (size_t)r*CC))[ul];
        __half2 q2 = *(__half2*)&qu;
        __half2 qp = __hmax2(q2, z2);
        __half2 qn = __hmax2(__hneg2(q2), z2);
        ((uint32_t*)(SA + r*APITCH))[ul]      = *(uint32_t*)&qp;
        ((uint32_t*)(SA + r*APITCH + 64))[ul] = *(uint32_t*)&qn;
    }
    // build B [72 n][128 k], 2-term split, inv_n folded
    const float* kvb = d_kvsum2 + (size_t)bh * 128 * 72;
    for (int idx = t; idx < 72*128; idx += 256) {
        int n = idx >> 7, k = idx & 127;
        int srcrow = ((n >= 32 && n < 64) || n == 65) ? ((k + 64) & 127) : k;
        int srccol = (n < 64) ? n : 64;
        float f = (n < 66) ? kvb[srcrow*72 + srccol] * invn : 0.f;
        __half hh = __float2half(f);
        SBH[n*APITCH + k] = hh;
        SBL[n*APITCH + k] = __float2half(f - __half2float(hh));
    }
    __syncthreads();

    float acc[9][4];
#pragma unroll
    for (int nt = 0; nt < 9; nt++)
#pragma unroll
        for (int r = 0; r < 4; r++) acc[nt][r] = 0.f;

    const int a_row = ((lane >> 3) & 1) * 8 + (lane & 7);
    const int a_koff = ((lane >> 4) & 1) * 8;
    const int b_row = ((lane >> 4) & 1) * 8 + (lane & 7);
    const int b_koff = ((lane >> 3) & 1) * 8;

#pragma unroll
    for (int k16 = 0; k16 < 8; ++k16) {
        const int ko = k16 * 16;
        uint32_t a[4];
        ldsm4(sb + AT2_SA + (uint32_t)(((m0 + a_row)*APITCH + ko + a_koff)*2),
              a[0], a[1], a[2], a[3]);
        uint32_t bhf[5][4], blf[5][4];
#pragma unroll
        for (int s = 0; s < 5; ++s) {
            uint32_t off = (uint32_t)(((s*16 + b_row)*APITCH + ko + b_koff)*2);
            ldsm4(sb + AT2_SBH + off, bhf[s][0], bhf[s][1], bhf[s][2], bhf[s][3]);
            ldsm4(sb + AT2_SBL + off, blf[s][0], blf[s][1], blf[s][2], blf[s][3]);
        }
#pragma unroll
        for (int nt = 0; nt < 9; ++nt)
            mma16816(acc[nt], a, &bhf[nt >> 1][(nt & 1) * 2]);
#pragma unroll
        for (int nt = 0; nt < 9; ++nt)
            mma16816(acc[nt], a, &blf[nt >> 1][(nt & 1) * 2]);
    }
    __syncthreads();

    // phase 2: accumulators -> smem, stage vpos/g, fused epilogue
    float* SACC = (float*)(sm + AT2_SACC);
    uint32_t* SVP = (uint32_t*)(sm + AT2_SVP);
    uint32_t* SG  = (uint32_t*)(sm + AT2_SG);
    uint32_t* AH  = (uint32_t*)(sm + AT2_AH);
    uint32_t* AL  = (uint32_t*)(sm + AT2_AL);

    const int gid = lane >> 2, tig = lane & 3;
#pragma unroll
    for (int nt = 0; nt < 9; ++nt) {
        int c0 = nt * 8 + tig * 2;
        SACC[(m0 + gid)*77 + c0]     = acc[nt][0];
        SACC[(m0 + gid)*77 + c0 + 1] = acc[nt][1];
        SACC[(m0 + 8 + gid)*77 + c0]     = acc[nt][2];
        SACC[(m0 + 8 + gid)*77 + c0 + 1] = acc[nt][3];
    }
#pragma unroll
    for (int i = 0; i < 16; ++i) {
        int idx = i * 256 + t;
        int r = idx >> 5, ul = idx & 31;
        SVP[r*33 + ul] = ((const uint32_t*)(d_vpos + blkbase + (size_t)r*CC))[ul];
        SG [r*33 + ul] = ((const uint32_t*)(d_g    + blkbase + (size_t)r*CC))[ul];
    }
    __syncthreads();

    {
        const int r = t & 127;
        const int chalf = t >> 7;               // 0: cols 0-31 (sim), 1: 32-63 (opp)
        float den = SACC[r*77 + 64 + chalf];
        float z = 1.f / (den + EPSV);
#pragma unroll
        for (int c4 = 0; c4 < 8; ++c4) {
            int c = chalf*32 + c4*4;
            float a0 = SACC[r*77 + c + 0] * z;
            float a1 = SACC[r*77 + c + 1] * z;
            float a2 = SACC[r*77 + c + 2] * z;
            float a3 = SACC[r*77 + c + 3] * z;
            uint32_t vu0 = SVP[r*33 + (c>>1)], vu1 = SVP[r*33 + (c>>1) + 1];
            uint32_t gu0 = SG [r*33 + (c>>1)], gu1 = SG [r*33 + (c>>1) + 1];
            float2 va = __half22float2(*(__half2*)&vu0);
            float2 vb = __half22float2(*(__half2*)&vu1);
            float2 ga = __half22float2(*(__half2*)&gu0);
            float2 gb = __half22float2(*(__half2*)&gu1);
            float r0 = (a0 + va.x) * ga.x;
            float r1 = (a1 + va.y) * ga.y;
            float r2 = (a2 + vb.x) * gb.x;
            float r3 = (a3 + vb.y) * gb.y;
            uint32_t h0 = 0, l0 = 0, h1 = 0, l1 = 0;
            split2h(r0, h0, l0, 0);  split2h(r1, h0, l0, 16);
            split2h(r2, h1, l1, 0);  split2h(r3, h1, l1, 16);
            AH[r*33 + (c>>1)]     = h0;
            AH[r*33 + (c>>1) + 1] = h1;
            AL[r*33 + (c>>1)]     = l0;
            AL[r*33 + (c>>1) + 1] = l1;
        }
    }
    __syncthreads();

#pragma unroll
    for (int rr = 0; rr < 16; ++rr) {
        int r = w * 16 + rr;
        ((uint32_t*)(d_acthi + blkbase + (size_t)r*CC))[lane] = AH[r*33 + lane];
        ((uint32_t*)(d_actlo + blkbase + (size_t)r*CC))[lane] = AL[r*33 + lane];
    }
}

// ---------------- depthwise conv (fp16 in/out) --------------------------------
__global__ void dwconv_kernel(const float* __restrict__ w,
                              const float* __restrict__ bias)
{
    const int bh = blockIdx.z;
    const int b = bh / HN, h = bh % HN;
    const int y = blockIdx.y;
    const int x = blockIdx.x * 4 + threadIdx.y;
    const int d = threadIdx.x;

    float wr[25];
#pragma unroll
    for (int i = 0; i < 25; i++) wr[i] = __ldg(&w[d*25 + i]);

    float acc = bias[d];
#pragma unroll
    for (int dy = 0; dy < 5; dy++) {
        int yy = y + dy - 2;
        if (yy < 0 || yy >= 64) continue;
#pragma unroll
        for (int dx = 0; dx < 5; dx++) {
            int xx = x + dx - 2;
            if (xx < 0 || xx >= 64) continue;
            acc += wr[dy*5 + dx] *
                   __half2float(d_v[((size_t)(b*NN + yy*64 + xx))*CC + h*64 + d]);
        }
    }
    d_vpos[((size_t)(b*NN + y*64 + x))*CC + h*64 + d] = __float2half(acc);
}

// ---------------- launcher ----------------------------------------------------
extern "C" void kernel_launch(void* const* d_in, const int* in_sizes, int n_in,
                              void* d_out, int out_size)
{
    const float* x       = (const float*)d_in[0];
    const float* Wqg     = (const float*)d_in[1];
    const float* Wkv     = (const float*)d_in[2];
    const float* Wproj   = (const float*)d_in[3];
    const float* bproj   = (const float*)d_in[4];
    const float* dwc_w   = (const float*)d_in[5];
    const float* dwc_b   = (const float*)d_in[6];
    const float* power_p = (const float*)d_in[7];
    const float* scale_p = (const float*)d_in[8];
    const float* pos_enc = (const float*)d_in[9];
    float* out = (float*)d_out;

    float *pis, *ppd;
    __half *pq, *pg, *pk, *pv;
    __half *pxh, *pxl, *pah, *pal;
    __half *pqgh, *pqgl, *pkvh, *pkvl, *pph, *ppl;
    cudaGetSymbolAddress((void**)&pq,  d_q);
    cudaGetSymbolAddress((void**)&pg,  d_g);
    cudaGetSymbolAddress((void**)&pk,  d_k);
    cudaGetSymbolAddress((void**)&pv,  d_v);
    cudaGetSymbolAddress((void**)&pis, d_invscale);
    cudaGetSymbolAddress((void**)&ppd, d_pdelta);
    cudaGetSymbolAddress((void**)&pxh, d_xhi);
    cudaGetSymbolAddress((void**)&pxl, d_xlo);
    cudaGetSymbolAddress((void**)&pah, d_acthi);
    cudaGetSymbolAddress((void**)&pal, d_actlo);
    cudaGetSymbolAddress((void**)&pqgh, d_wqgt_h);
    cudaGetSymbolAddress((void**)&pqgl, d_wqgt_l);
    cudaGetSymbolAddress((void**)&pkvh, d_wkvt_h);
    cudaGetSymbolAddress((void**)&pkvl, d_wkvt_l);
    cudaGetSymbolAddress((void**)&pph, d_wpt_h);
    cudaGetSymbolAddress((void**)&ppl, d_wpt_l);

    cudaFuncSetAttribute(mma_gemm<0>, cudaFuncAttributeMaxDynamicSharedMemorySize, SM_TOTAL);
    cudaFuncSetAttribute(mma_gemm<1>, cudaFuncAttributeMaxDynamicSharedMemorySize, SM_TOTAL);
    cudaFuncSetAttribute(mma_gemm<2>, cudaFuncAttributeMaxDynamicSharedMemorySize, SM_TOTAL);
    cudaFuncSetAttribute(kvstate_kernel, cudaFuncAttributeMaxDynamicSharedMemorySize, KV_TOTAL);
    cudaFuncSetAttribute(attn_kernel, cudaFuncAttributeMaxDynamicSharedMemorySize, AT2_TOTAL);

    params_kernel<<<1, CC>>>(scale_p, power_p);

    convert_split_kernel<<<(ROWS*CC/4)/256, 256>>>(x, pxh, pxl);
    wtrans_kernel<<<dim3(2*CC/32, CC/32), dim3(32, 8)>>>(Wqg, pqgh, pqgl, 2*CC);
    wtrans_kernel<<<dim3(2*CC/32, CC/32), dim3(32, 8)>>>(Wkv, pkvh, pkvl, 2*CC);
    wtrans_kernel<<<dim3(CC/32,   CC/32), dim3(32, 8)>>>(Wproj, pph, ppl, CC);

    // qg = x @ Wqg (q: 3-term + scaled pow epilogue; g: 2-term)
    mma_gemm<0><<<dim3(2*CC/TN, ROWS/TM), 256, SM_TOTAL>>>(
        pxh, pxl, pqgh, pqgl, pis, nullptr, ppd, pq, pg);
    // kv = x @ Wkv (k: 3-term + pos_enc/scale/pow epilogue; v: 2-term)
    mma_gemm<1><<<dim3(2*CC/TN, ROWS/TM), 256, SM_TOTAL>>>(
        pxh, pxl, pkvh, pkvl, pis, pos_enc, ppd, pk, pv);

    kvstate_kernel<<<BB*HN, 256, KV_TOTAL>>>();
    dwconv_kernel<<<dim3(16, 64, BB*HN), dim3(64, 4)>>>(dwc_w, dwc_b);
    attn_kernel<<<dim3(NN/128, BB*HN), 256, AT2_TOTAL>>>();

    // out = act @ Wproj + bproj (2-term)
    mma_gemm<2><<<dim3(CC/TN, ROWS/TM), 256, SM_TOTAL>>>(
        pah, pal, pph, ppl, bproj, nullptr, nullptr, out, nullptr);
}

// round 15
// speedup vs baseline: 1.0044x; 1.0027x over previous
#include <cuda_runtime.h>
#include <cuda_fp16.h>
#include <math.h>
#include <cstdint>

#define BB 8
#define NN 4096
#define CC 768
#define HN 12
#define HD 64
#define ROWS (BB*NN)
#define EPSV 1e-6f

// ---- HMMA GEMM tiling ----
#define TM 128
#define TN 128
#define KC 64
#define NCHUNK (CC/KC)             // 12
#define ROWB 144                   // padded smem row stride (bytes) for 64 fp16
#define TILE_BYTES (128*ROWB)      // 18432
#define STAGE_BYTES (4*TILE_BYTES) // Ah,Al,Bh,Bl = 73728
#define SM_TOTAL (2*STAGE_BYTES)   // 147456

// ---- kvstate kernel smem ----
#define KCH 128
#define KV_SV 34816                           // SK [128][136]h then SV [128][72]h
#define KV_TOTAL (34816 + 18432 + 2048)       // + slack for paired-ldsm overread

// ---- attn kernel smem (two overlapping phases) ----
#define APITCH 136
#define AT2_SA   0                 // phase1: A qsim [128][136] h
#define AT2_SBH  34816             // phase1: Bh [72][136] h
#define AT2_SBL  54400             // phase1: Bl [72][136] h (ends 73984)
#define AT2_SACC 0                 // phase2: f32 [128][77] = 39424
#define AT2_SVP  39424             // phase2: uint [128][33]
#define AT2_SG   56320             // phase2: uint [128][33]
#define AT2_AH   73216             // phase2: uint [128][33]
#define AT2_AL   90112             // phase2: uint [128][33]
#define AT2_TOTAL 107008

// ---------------- scratch (device globals; no allocations allowed) ----------
__device__ __half d_q[ROWS*CC];     // signed pow of q (fp16)
__device__ __half d_g[ROWS*CC];
__device__ __half d_k[ROWS*CC];     // signed pow of k (fp16)
__device__ __half d_v[ROWS*CC];
__device__ __half d_vpos[ROWS*CC];
__device__ float d_kvsum2[BB*HN*128*72];   // per bh: [128 ch_cat][72] (64 kv + ksum + pad)
__device__ float d_invscale[CC];
__device__ float d_pdelta[CC];      // power - 3
__device__ __half d_xhi[ROWS*CC];
__device__ __half d_xlo[ROWS*CC];
__device__ __half d_acthi[ROWS*CC];
__device__ __half d_actlo[ROWS*CC];
__device__ __half d_wqgt_h[2*CC*CC];
__device__ __half d_wqgt_l[2*CC*CC];
__device__ __half d_wkvt_h[2*CC*CC];
__device__ __half d_wkvt_l[2*CC*CC];
__device__ __half d_wpt_h[CC*CC];
__device__ __half d_wpt_l[CC*CC];

// ---------------- PTX helpers -------------------------------------------------
__device__ __forceinline__ uint32_t smem_u32(const void* p) {
    uint32_t a;
    asm("{ .reg .u64 t; cvta.to.shared.u64 t, %1; cvt.u32.u64 %0, t; }" : "=r"(a) : "l"(p));
    return a;
}

__device__ __forceinline__ void cp_async16(uint32_t dst, const void* src) {
    asm volatile("cp.async.cg.shared.global [%0], [%1], 16;" :: "r"(dst), "l"(src));
}
__device__ __forceinline__ void cp_commit() {
    asm volatile("cp.async.commit_group;");
}
template<int N>
__device__ __forceinline__ void cp_wait() {
    asm volatile("cp.async.wait_group %0;" :: "n"(N));
}

__device__ __forceinline__ void ldsm4(uint32_t addr, uint32_t& r0, uint32_t& r1,
                                      uint32_t& r2, uint32_t& r3) {
    asm volatile("ldmatrix.sync.aligned.m8n8.x4.shared.b16 {%0,%1,%2,%3}, [%4];"
                 : "=r"(r0), "=r"(r1), "=r"(r2), "=r"(r3) : "r"(addr));
}

__device__ __forceinline__ void ldsm4t(uint32_t addr, uint32_t& r0, uint32_t& r1,
                                       uint32_t& r2, uint32_t& r3) {
    asm volatile("ldmatrix.sync.aligned.m8n8.x4.trans.shared.b16 {%0,%1,%2,%3}, [%4];"
                 : "=r"(r0), "=r"(r1), "=r"(r2), "=r"(r3) : "r"(addr));
}

__device__ __forceinline__ void mma16816(float* c, const uint32_t* a, const uint32_t* b) {
    asm volatile(
        "mma.sync.aligned.m16n8k16.row.col.f32.f16.f16.f32 "
        "{%0,%1,%2,%3}, {%4,%5,%6,%7}, {%8,%9}, {%0,%1,%2,%3};"
        : "+f"(c[0]), "+f"(c[1]), "+f"(c[2]), "+f"(c[3])
        : "r"(a[0]), "r"(a[1]), "r"(a[2]), "r"(a[3]), "r"(b[0]), "r"(b[1]));
}

// ---------------- MUFU-free signed pow: sign(x)*|x|^(3+delta) ----------------
__device__ __forceinline__ float spow_fast(float x, float delta)
{
    float ax = fabsf(x);
    int i = __float_as_int(ax);
    int e = ((i >> 23) & 0xFF) - 127;
    float m = __int_as_float((i & 0x7FFFFF) | 0x3F800000);
    if (m > 1.41421356f) { m *= 0.5f; e += 1; }
    float t = m - 1.0f;
    float p = -0.125f;
    p = fmaf(p, t, 0.14285714f);
    p = fmaf(p, t, -0.16666667f);
    p = fmaf(p, t, 0.2f);
    p = fmaf(p, t, -0.25f);
    p = fmaf(p, t, 0.33333333f);
    p = fmaf(p, t, -0.5f);
    p = fmaf(p, t, 1.0f);
    float lnax = fmaf((float)e, 0.69314718f, t * p);
    float u = delta * lnax;
    float eu = fmaf(u, 0.04166667f, 0.16666667f);
    eu = fmaf(eu, u, 0.5f);
    eu = fmaf(eu, u, 1.0f);
    eu = fmaf(eu, u, 1.0f);
    float r = ax * ax * ax * eu;
    r = copysignf(r, x);
    return (ax > 0.f) ? r : 0.f;
}

// ---------------- params ------------------------------------------------------
__global__ void params_kernel(const float* __restrict__ scale_p,
                              const float* __restrict__ power_p)
{
    int c = threadIdx.x;
    if (c < CC) {
        float sp = scale_p[c];
        float sc = (sp > 20.f) ? sp : log1pf(__expf(sp));
        d_invscale[c] = 1.f / sc;
        float pp = power_p[c];
        d_pdelta[c] = 4.f / (1.f + __expf(-pp)) - 2.f;
    }
}

// ---------------- fp32 -> (hi,lo) fp16 split ---------------------------------
__device__ __forceinline__ void split2h(float v, uint32_t& hi, uint32_t& lo, int shift)
{
    __half h = __float2half(v);
    __half l = __float2half(v - __half2float(h));
    hi |= (uint32_t)__half_as_ushort(h) << shift;
    lo |= (uint32_t)__half_as_ushort(l) << shift;
}

__global__ void convert_split_kernel(const float* __restrict__ in,
                                     __half* __restrict__ hi,
                                     __half* __restrict__ lo)
{
    size_t i = ((size_t)blockIdx.x * blockDim.x + threadIdx.x) * 4;
    float4 v = *(const float4*)(in + i);
    uint32_t h0 = 0, l0 = 0, h1 = 0, l1 = 0;
    split2h(v.x, h0, l0, 0);  split2h(v.y, h0, l0, 16);
    split2h(v.z, h1, l1, 0);  split2h(v.w, h1, l1, 16);
    *(uint2*)(hi + i) = make_uint2(h0, h1);
    *(uint2*)(lo + i) = make_uint2(l0, l1);
}

// W [K=768, Nw] -> Wt split-fp16 [Nw, 768]
__global__ void wtrans_kernel(const float* __restrict__ W,
                              __half* __restrict__ hi,
                              __half* __restrict__ lo, int Nw)
{
    __shared__ float tile[32][33];
    int n0 = blockIdx.x * 32, k0 = blockIdx.y * 32;
    int tx = threadIdx.x, ty = threadIdx.y;
#pragma unroll
    for (int i = 0; i < 4; i++)
        tile[ty + i*8][tx] = W[(size_t)(k0 + ty + i*8) * Nw + n0 + tx];
    __syncthreads();
#pragma unroll
    for (int i = 0; i < 4; i++) {
        float v = tile[tx][ty + i*8];
        __half h = __float2half(v);
        __half l = __float2half(v - __half2float(h));
        size_t o = (size_t)(n0 + ty + i*8) * CC + k0 + tx;
        hi[o] = h; lo[o] = l;
    }
}

// ---------------- HMMA split-fp16 GEMM (unchanged from R8 best) ---------------
template<int MODE>
__global__ __launch_bounds__(256, 1)
void mma_gemm(const __half* __restrict__ Ah_g, const __half* __restrict__ Al_g,
              const __half* __restrict__ Bh_g, const __half* __restrict__ Bl_g,
              const float* __restrict__ aux0, const float* __restrict__ aux1,
              const float* __restrict__ pdelta,
              void* __restrict__ out0v, void* __restrict__ out1v)
{
    extern __shared__ char smem[];
    const int tid = threadIdx.x;
    const int rowBase = blockIdx.y * TM;
    const int colBase = blockIdx.x * TN;
    const bool third = (MODE != 2) && (colBase < CC);
    const uint32_t sbase = smem_u32(smem);

    const int lane = tid & 31;
    const int w = tid >> 5;
    const int m0 = (w >> 2) * 64;
    const int n0 = (w & 3) * 32;

    const __half* srcs[4] = { Ah_g, Al_g, Bh_g, Bl_g };

    float acc[4][4][4];
#pragma unroll
    for (int i = 0; i < 4; i++)
#pragma unroll
        for (int j = 0; j < 4; j++)
#pragma unroll
            for (int r = 0; r < 4; r++) acc[i][j][r] = 0.f;

    auto issue_loads = [&](int ch, int stage) {
        const int k0 = ch * KC;
        const uint32_t sb = sbase + stage * STAGE_BYTES;
#pragma unroll
        for (int it = 0; it < 16; ++it) {
            int id = it * 256 + tid;
            int which = id >> 10;
            if (which == 1 && !third) continue;
            int rem = id & 1023;
            int row = rem >> 3;
            int q = rem & 7;
            int grow = (which < 2) ? (rowBase + row) : (colBase + row);
            const __half* src = srcs[which] + (size_t)grow * CC + k0 + q * 8;
            cp_async16(sb + which * TILE_BYTES + row * ROWB + q * 16, src);
        }
        cp_commit();
    };

    issue_loads(0, 0);

    const int a_row = ((lane >> 3) & 1) * 8 + (lane & 7);
    const int a_koff = ((lane >> 4) & 1) * 8;
    const int b_row = ((lane >> 4) & 1) * 8 + (lane & 7);
    const int b_koff = ((lane >> 3) & 1) * 8;

    for (int ch = 0; ch < NCHUNK; ++ch) {
        const int stage = ch & 1;
        cp_wait<0>();
        __syncthreads();
        if (ch + 1 < NCHUNK)
            issue_loads(ch + 1, (ch + 1) & 1);

        const uint32_t sb = sbase + stage * STAGE_BYTES;
        const uint32_t sAh = sb;
        const uint32_t sAl = sb + TILE_BYTES;
        const uint32_t sBh = sb + 2 * TILE_BYTES;
        const uint32_t sBl = sb + 3 * TILE_BYTES;

#pragma unroll
        for (int k16 = 0; k16 < KC / 16; ++k16) {
            const int ko = k16 * 16;
            uint32_t ah[4][4], al[4][4], bh[2][4], bl[2][4];
#pragma unroll
            for (int mi = 0; mi < 4; ++mi) {
                uint32_t off = (uint32_t)((m0 + mi * 16 + a_row) * ROWB + (ko + a_koff) * 2);
                ldsm4(sAh + off, ah[mi][0], ah[mi][1], ah[mi][2], ah[mi][3]);
                if (third)
                    ldsm4(sAl + off, al[mi][0], al[mi][1], al[mi][2], al[mi][3]);
            }
#pragma unroll
            for (int j = 0; j < 2; ++j) {
                uint32_t off = (uint32_t)((n0 + j * 16 + b_row) * ROWB + (ko + b_koff) * 2);
                ldsm4(sBh + off, bh[j][0], bh[j][1], bh[j][2], bh[j][3]);
                ldsm4(sBl + off, bl[j][0], bl[j][1], bl[j][2], bl[j][3]);
            }
#pragma unroll
            for (int mi = 0; mi < 4; ++mi)
#pragma unroll
                for (int nt = 0; nt < 4; ++nt)
                    mma16816(acc[mi][nt], ah[mi], &bh[nt >> 1][(nt & 1) * 2]);
#pragma unroll
            for (int mi = 0; mi < 4; ++mi)
#pragma unroll
                for (int nt = 0; nt < 4; ++nt)
                    mma16816(acc[mi][nt], ah[mi], &bl[nt >> 1][(nt & 1) * 2]);
            if (third) {
#pragma unroll
                for (int mi = 0; mi < 4; ++mi)
#pragma unroll
                    for (int nt = 0; nt < 4; ++nt)
                        mma16816(acc[mi][nt], al[mi], &bh[nt >> 1][(nt & 1) * 2]);
            }
        }
        __syncthreads();
    }

    const int gid = lane >> 2, tig = lane & 3;
#pragma unroll
    for (int mi = 0; mi < 4; ++mi) {
#pragma unroll
        for (int nt = 0; nt < 4; ++nt) {
            int r0 = rowBase + m0 + mi * 16 + gid;
            int c = colBase + n0 + nt * 8 + tig * 2;
#pragma unroll
            for (int half = 0; half < 2; ++half) {
                int r = r0 + half * 8;
                float v0 = acc[mi][nt][half * 2 + 0];
                float v1 = acc[mi][nt][half * 2 + 1];
                if (MODE == 0) {
                    if (c < CC) {
                        float q0 = spow_fast(v0 * aux0[c],     pdelta[c]);
                        float q1 = spow_fast(v1 * aux0[c + 1], pdelta[c + 1]);
                        *(__half2*)((__half*)out0v + (size_t)r * CC + c) = __floats2half2_rn(q0, q1);
                    } else {
                        *(__half2*)((__half*)out1v + (size_t)r * CC + c - CC) = __floats2half2_rn(v0, v1);
                    }
                } else if (MODE == 1) {
                    if (c < CC) {
                        const float* pe = aux1 + (size_t)(r & (NN - 1)) * CC + c;
                        float k0v = spow_fast((v0 + pe[0]) * aux0[c],     pdelta[c]);
                        float k1v = spow_fast((v1 + pe[1]) * aux0[c + 1], pdelta[c + 1]);
                        *(__half2*)((__half*)out0v + (size_t)r * CC + c) = __floats2half2_rn(k0v, k1v);
                    } else {
                        *(__half2*)((__half*)out1v + (size_t)r * CC + c - CC) = __floats2half2_rn(v0, v1);
                    }
                } else {
                    float2 o = make_float2(v0 + aux0[c], v1 + aux0[c + 1]);
                    *(float2*)((float*)out0v + (size_t)r * CC + c) = o;
                }
            }
        }
    }
}

// ---------------- kv-state via HMMA: per bh  kcat^T[128x4096] @ [v|1] --------
__global__ __launch_bounds__(256)
void kvstate_kernel()
{
    extern __shared__ char sm[];
    __half* SK = (__half*)sm;                 // [KCH][136]
    __half* SV = (__half*)(sm + KV_SV);       // [KCH][72]
    const uint32_t sb = smem_u32(sm);

    const int bh = blockIdx.x;
    const int b = bh / HN, h = bh % HN;
    const int t = threadIdx.x;
    const int w = t >> 5, lane = t & 31;
    const int m0 = w * 16;

    if (t < KCH) {
        SV[t*72 + 64] = __float2half(1.f);
#pragma unroll
        for (int j = 65; j < 72; j++) SV[t*72 + j] = __float2half(0.f);
    }

    float acc[9][4];
#pragma unroll
    for (int nt = 0; nt < 9; nt++)
#pragma unroll
        for (int r = 0; r < 4; r++) acc[nt][r] = 0.f;

    const int a_tok = ((lane >> 4) & 1) * 8 + (lane & 7);
    const int a_moff = ((lane >> 3) & 1) * 8;
    const int b_tok = ((lane >> 3) & 1) * 8 + (lane & 7);
    const int b_noff = ((lane >> 4) & 1) * 8;
    const __half2 z2 = __floats2half2_rn(0.f, 0.f);

    for (int ch = 0; ch < NN / KCH; ++ch) {
#pragma unroll
        for (int i = 0; i < (KCH*32)/256; ++i) {
            int idx = i * 256 + t;
            int r = idx >> 5, ul = idx & 31;
            size_t base = ((size_t)(b*NN + ch*KCH + r))*CC + h*64;
            uint32_t ku = ((const uint32_t*)(d_k + base))[ul];
            uint32_t vu = ((const uint32_t*)(d_v + base))[ul];
            __half2 k2 = *(__half2*)&ku;
            __half2 kp = __hmax2(k2, z2);
            __half2 kn = __hmax2(__hneg2(k2), z2);
            ((uint32_t*)(SK + r*136))[ul]      = *(uint32_t*)&kp;
            ((uint32_t*)(SK + r*136 + 64))[ul] = *(uint32_t*)&kn;
            ((uint32_t*)(SV + r*72))[ul]       = vu;
        }
        __syncthreads();
#pragma unroll
        for (int k16 = 0; k16 < KCH/16; ++k16) {
            const int ko = k16 * 16;
            uint32_t a[4];
            ldsm4t(sb + (uint32_t)(((ko + a_tok)*136 + m0 + a_moff)*2),
                   a[0], a[1], a[2], a[3]);
            uint32_t bf[5][4];
#pragma unroll
            for (int s = 0; s < 5; ++s)
                ldsm4t(sb + KV_SV + (uint32_t)(((ko + b_tok)*72 + s*16 + b_noff)*2),
                       bf[s][0], bf[s][1], bf[s][2], bf[s][3]);
#pragma unroll
            for (int nt = 0; nt < 9; ++nt)
                mma16816(acc[nt], a, &bf[nt >> 1][(nt & 1) * 2]);
        }
        __syncthreads();
    }

    const int gid = lane >> 2, tig = lane & 3;
    float* outp = d_kvsum2 + (size_t)bh * 128 * 72;
#pragma unroll
    for (int nt = 0; nt < 9; ++nt) {
        int c0 = nt * 8 + tig * 2;
        outp[(m0 + gid)*72 + c0]     = acc[nt][0];
        outp[(m0 + gid)*72 + c0 + 1] = acc[nt][1];
        outp[(m0 + 8 + gid)*72 + c0]     = acc[nt][2];
        outp[(m0 + 8 + gid)*72 + c0 + 1] = acc[nt][3];
    }
}

// ---------------- attn via HMMA: qsim[128x128] @ B[128x72] + fused epilogue ---
__global__ __launch_bounds__(256)
void attn_kernel()
{
    extern __shared__ char sm[];
    __half* SA  = (__half*)(sm + AT2_SA);
    __half* SBH = (__half*)(sm + AT2_SBH);
    __half* SBL = (__half*)(sm + AT2_SBL);
    const uint32_t sb = smem_u32(sm);

    const int bh = blockIdx.y;
    const int b = bh / HN, h = bh % HN;
    const int ntile = blockIdx.x;
    const int t = threadIdx.x;
    const int w = t >> 5, lane = t & 31;
    const int m0 = w * 16;
    const size_t blkbase = ((size_t)(b*NN + ntile*128))*CC + h*64;
    const float invn = 1.f / (float)NN;
    const __half2 z2 = __floats2half2_rn(0.f, 0.f);

    // build A = q_sim [128 r][128 ch] (pos | neg), exact from fp16 q
#pragma unroll
    for (int i = 0; i < 16; ++i) {
        int idx = i * 256 + t;
        int r = idx >> 5, ul = idx & 31;
        uint32_t qu = ((const uint32_t*)(d_q + blkbase + (size_t)r*CC))[ul];
        __half2 q2 = *(__half2*)&qu;
        __half2 qp = __hmax2(q2, z2);
        __half2 qn = __hmax2(__hneg2(q2), z2);
        ((uint32_t*)(SA + r*APITCH))[ul]      = *(uint32_t*)&qp;
        ((uint32_t*)(SA + r*APITCH + 64))[ul] = *(uint32_t*)&qn;
    }
    // build B [72 n][128 k], 2-term split, inv_n folded
    const float* kvb = d_kvsum2 + (size_t)bh * 128 * 72;
    for (int idx = t; idx < 72*128; idx += 256) {
        int n = idx >> 7, k = idx & 127;
        int srcrow = ((n >= 32 && n < 64) || n == 65) ? ((k + 64) & 127) : k;
        int srccol = (n < 64) ? n : 64;
        float f = (n < 66) ? kvb[srcrow*72 + srccol] * invn : 0.f;
        __half hh = __float2half(f);
        SBH[n*APITCH + k] = hh;
        SBL[n*APITCH + k] = __float2half(f - __half2float(hh));
    }
    __syncthreads();

    float acc[9][4];
#pragma unroll
    for (int nt = 0; nt < 9; nt++)
#pragma unroll
        for (int r = 0; r < 4; r++) acc[nt][r] = 0.f;

    const int a_row = ((lane >> 3) & 1) * 8 + (lane & 7);
    const int a_koff = ((lane >> 4) & 1) * 8;
    const int b_row = ((lane >> 4) & 1) * 8 + (lane & 7);
    const int b_koff = ((lane >> 3) & 1) * 8;

#pragma unroll
    for (int k16 = 0; k16 < 8; ++k16) {
        const int ko = k16 * 16;
        uint32_t a[4];
        ldsm4(sb + AT2_SA + (uint32_t)(((m0 + a_row)*APITCH + ko + a_koff)*2),
              a[0], a[1], a[2], a[3]);
        uint32_t bhf[5][4], blf[5][4];
#pragma unroll
        for (int s = 0; s < 5; ++s) {
            uint32_t off = (uint32_t)(((s*16 + b_row)*APITCH + ko + b_koff)*2);
            ldsm4(sb + AT2_SBH + off, bhf[s][0], bhf[s][1], bhf[s][2], bhf[s][3]);
            ldsm4(sb + AT2_SBL + off, blf[s][0], blf[s][1], blf[s][2], blf[s][3]);
        }
#pragma unroll
        for (int nt = 0; nt < 9; ++nt)
            mma16816(acc[nt], a, &bhf[nt >> 1][(nt & 1) * 2]);
#pragma unroll
        for (int nt = 0; nt < 9; ++nt)
            mma16816(acc[nt], a, &blf[nt >> 1][(nt & 1) * 2]);
    }
    __syncthreads();

    // phase 2: accumulators -> smem, stage vpos/g, fused epilogue
    float* SACC = (float*)(sm + AT2_SACC);
    uint32_t* SVP = (uint32_t*)(sm + AT2_SVP);
    uint32_t* SG  = (uint32_t*)(sm + AT2_SG);
    uint32_t* AH  = (uint32_t*)(sm + AT2_AH);
    uint32_t* AL  = (uint32_t*)(sm + AT2_AL);

    const int gid = lane >> 2, tig = lane & 3;
#pragma unroll
    for (int nt = 0; nt < 9; ++nt) {
        int c0 = nt * 8 + tig * 2;
        SACC[(m0 + gid)*77 + c0]     = acc[nt][0];
        SACC[(m0 + gid)*77 + c0 + 1] = acc[nt][1];
        SACC[(m0 + 8 + gid)*77 + c0]     = acc[nt][2];
        SACC[(m0 + 8 + gid)*77 + c0 + 1] = acc[nt][3];
    }
#pragma unroll
    for (int i = 0; i < 16; ++i) {
        int idx = i * 256 + t;
        int r = idx >> 5, ul = idx & 31;
        SVP[r*33 + ul] = ((const uint32_t*)(d_vpos + blkbase + (size_t)r*CC))[ul];
        SG [r*33 + ul] = ((const uint32_t*)(d_g    + blkbase + (size_t)r*CC))[ul];
    }
    __syncthreads();

    {
        const int r = t & 127;
        const int chalf = t >> 7;               // 0: cols 0-31 (sim), 1: 32-63 (opp)
        float den = SACC[r*77 + 64 + chalf];
        float z = 1.f / (den + EPSV);
#pragma unroll
        for (int c4 = 0; c4 < 8; ++c4) {
            int c = chalf*32 + c4*4;
            float a0 = SACC[r*77 + c + 0] * z;
            float a1 = SACC[r*77 + c + 1] * z;
            float a2 = SACC[r*77 + c + 2] * z;
            float a3 = SACC[r*77 + c + 3] * z;
            uint32_t vu0 = SVP[r*33 + (c>>1)], vu1 = SVP[r*33 + (c>>1) + 1];
            uint32_t gu0 = SG [r*33 + (c>>1)], gu1 = SG [r*33 + (c>>1) + 1];
            float2 va = __half22float2(*(__half2*)&vu0);
            float2 vb = __half22float2(*(__half2*)&vu1);
            float2 ga = __half22float2(*(__half2*)&gu0);
            float2 gb = __half22float2(*(__half2*)&gu1);
            float r0 = (a0 + va.x) * ga.x;
            float r1 = (a1 + va.y) * ga.y;
            float r2 = (a2 + vb.x) * gb.x;
            float r3 = (a3 + vb.y) * gb.y;
            uint32_t h0 = 0, l0 = 0, h1 = 0, l1 = 0;
            split2h(r0, h0, l0, 0);  split2h(r1, h0, l0, 16);
            split2h(r2, h1, l1, 0);  split2h(r3, h1, l1, 16);
            AH[r*33 + (c>>1)]     = h0;
            AH[r*33 + (c>>1) + 1] = h1;
            AL[r*33 + (c>>1)]     = l0;
            AL[r*33 + (c>>1) + 1] = l1;
        }
    }
    __syncthreads();

#pragma unroll
    for (int rr = 0; rr < 16; ++rr) {
        int r = w * 16 + rr;
        ((uint32_t*)(d_acthi + blkbase + (size_t)r*CC))[lane] = AH[r*33 + lane];
        ((uint32_t*)(d_actlo + blkbase + (size_t)r*CC))[lane] = AL[r*33 + lane];
    }
}

// ---------------- depthwise conv (fp16 in/out) --------------------------------
__global__ void dwconv_kernel(const float* __restrict__ w,
                              const float* __restrict__ bias)
{
    const int bh = blockIdx.z;
    const int b = bh / HN, h = bh % HN;
    const int y = blockIdx.y;
    const int x = blockIdx.x * 4 + threadIdx.y;
    const int d = threadIdx.x;

    float wr[25];
#pragma unroll
    for (int i = 0; i < 25; i++) wr[i] = __ldg(&w[d*25 + i]);

    float acc = bias[d];
#pragma unroll
    for (int dy = 0; dy < 5; dy++) {
        int yy = y + dy - 2;
        if (yy < 0 || yy >= 64) continue;
#pragma unroll
        for (int dx = 0; dx < 5; dx++) {
            int xx = x + dx - 2;
            if (xx < 0 || xx >= 64) continue;
            acc += wr[dy*5 + dx] *
                   __half2float(d_v[((size_t)(b*NN + yy*64 + xx))*CC + h*64 + d]);
        }
    }
    d_vpos[((size_t)(b*NN + y*64 + x))*CC + h*64 + d] = __float2half(acc);
}

// ---------------- launcher ----------------------------------------------------
extern "C" void kernel_launch(void* const* d_in, const int* in_sizes, int n_in,
                              void* d_out, int out_size)
{
    const float* x       = (const float*)d_in[0];
    const float* Wqg     = (const float*)d_in[1];
    const float* Wkv     = (const float*)d_in[2];
    const float* Wproj   = (const float*)d_in[3];
    const float* bproj   = (const float*)d_in[4];
    const float* dwc_w   = (const float*)d_in[5];
    const float* dwc_b   = (const float*)d_in[6];
    const float* power_p = (const float*)d_in[7];
    const float* scale_p = (const float*)d_in[8];
    const float* pos_enc = (const float*)d_in[9];
    float* out = (float*)d_out;

    float *pis, *ppd;
    __half *pq, *pg, *pk, *pv;
    __half *pxh, *pxl, *pah, *pal;
    __half *pqgh, *pqgl, *pkvh, *pkvl, *pph, *ppl;
    cudaGetSymbolAddress((void**)&pq,  d_q);
    cudaGetSymbolAddress((void**)&pg,  d_g);
    cudaGetSymbolAddress((void**)&pk,  d_k);
    cudaGetSymbolAddress((void**)&pv,  d_v);
    cudaGetSymbolAddress((void**)&pis, d_invscale);
    cudaGetSymbolAddress((void**)&ppd, d_pdelta);
    cudaGetSymbolAddress((void**)&pxh, d_xhi);
    cudaGetSymbolAddress((void**)&pxl, d_xlo);
    cudaGetSymbolAddress((void**)&pah, d_acthi);
    cudaGetSymbolAddress((void**)&pal, d_actlo);
    cudaGetSymbolAddress((void**)&pqgh, d_wqgt_h);
    cudaGetSymbolAddress((void**)&pqgl, d_wqgt_l);
    cudaGetSymbolAddress((void**)&pkvh, d_wkvt_h);
    cudaGetSymbolAddress((void**)&pkvl, d_wkvt_l);
    cudaGetSymbolAddress((void**)&pph, d_wpt_h);
    cudaGetSymbolAddress((void**)&ppl, d_wpt_l);

    cudaFuncSetAttribute(mma_gemm<0>, cudaFuncAttributeMaxDynamicSharedMemorySize, SM_TOTAL);
    cudaFuncSetAttribute(mma_gemm<1>, cudaFuncAttributeMaxDynamicSharedMemorySize, SM_TOTAL);
    cudaFuncSetAttribute(mma_gemm<2>, cudaFuncAttributeMaxDynamicSharedMemorySize, SM_TOTAL);
    cudaFuncSetAttribute(kvstate_kernel, cudaFuncAttributeMaxDynamicSharedMemorySize, KV_TOTAL);
    cudaFuncSetAttribute(attn_kernel, cudaFuncAttributeMaxDynamicSharedMemorySize, AT2_TOTAL);

    params_kernel<<<1, CC>>>(scale_p, power_p);

    convert_split_kernel<<<(ROWS*CC/4)/256, 256>>>(x, pxh, pxl);
    wtrans_kernel<<<dim3(2*CC/32, CC/32), dim3(32, 8)>>>(Wqg, pqgh, pqgl, 2*CC);
    wtrans_kernel<<<dim3(2*CC/32, CC/32), dim3(32, 8)>>>(Wkv, pkvh, pkvl, 2*CC);
    wtrans_kernel<<<dim3(CC/32,   CC/32), dim3(32, 8)>>>(Wproj, pph, ppl, CC);

    // qg = x @ Wqg (q: 3-term + scaled pow epilogue; g: 2-term)
    mma_gemm<0><<<dim3(2*CC/TN, ROWS/TM), 256, SM_TOTAL>>>(
        pxh, pxl, pqgh, pqgl, pis, nullptr, ppd, pq, pg);
    // kv = x @ Wkv (k: 3-term + pos_enc/scale/pow epilogue; v: 2-term)
    mma_gemm<1><<<dim3(2*CC/TN, ROWS/TM), 256, SM_TOTAL>>>(
        pxh, pxl, pkvh, pkvl, pis, pos_enc, ppd, pk, pv);

    kvstate_kernel<<<BB*HN, 256, KV_TOTAL>>>();
    dwconv_kernel<<<dim3(16, 64, BB*HN), dim3(64, 4)>>>(dwc_w, dwc_b);
    attn_kernel<<<dim3(NN/128, BB*HN), 256, AT2_TOTAL>>>();

    // out = act @ Wproj + bproj (2-term)
    mma_gemm<2><<<dim3(CC/TN, ROWS/TM), 256, SM_TOTAL>>>(
        pah, pal, pph, ppl, bproj, nullptr, nullptr, out, nullptr);
}